// round 4
// baseline (speedup 1.0000x reference)
#include <cuda_runtime.h>
#include <cuda_fp16.h>

// LTC RNN, B=256 T=8192 I=6 U=64 M=16, 6 ODE unfolds. MUFU(XU)-bound.
// Round-4: hybrid precision by UNFOLD. Unfolds 0-3 use tanh.approx.f16x2
// (args f32, accumulation exact f32 via fma.rn.f32x2); unfolds 4-5 use
// f32 tanh.approx so fp16 noise is damped by the ODE map's contraction
// before it reaches the timestep output. Plus anti-phase stagger: CTAs with
// bid>=148 (co-resident with bid-148 under classic placement) burn a
// dependent-MUFU chain once so the two CTAs' per-unfold serial tails
// interleave with each other's MUFU bursts instead of phase-locking.

#define T_LEN 8192
#define NI 6
#define NU 64
#define NM 16

typedef unsigned long long u64;
typedef unsigned int u32;

static __device__ __forceinline__ float fast_tanh(float x) {
    float r; asm("tanh.approx.f32 %0, %1;" : "=f"(r) : "f"(x)); return r;
}
static __device__ __forceinline__ u64 pack2(float lo, float hi) {
    u64 r; asm("mov.b64 %0, {%1, %2};" : "=l"(r) : "f"(lo), "f"(hi)); return r;
}
static __device__ __forceinline__ u64 fma2(u64 a, u64 b, u64 c) {
    u64 d; asm("fma.rn.f32x2 %0, %1, %2, %3;" : "=l"(d) : "l"(a), "l"(b), "l"(c));
    return d;
}
static __device__ __forceinline__ void unpack2(u64 v, float& lo, float& hi) {
    asm("mov.b64 {%0, %1}, %2;" : "=f"(lo), "=f"(hi) : "l"(v));
}
// f32 pair -> f16x2 tanh -> two f32
static __device__ __forceinline__ void tanh2_f16(u64 arg2, float& h0, float& h1) {
    u32 p;
    asm("{\n .reg .f32 lo, hi;\n"
        "  mov.b64 {lo, hi}, %1;\n"
        "  cvt.rn.f16x2.f32 %0, hi, lo;\n}" : "=r"(p) : "l"(arg2));
    asm("tanh.approx.f16x2 %0, %0;" : "+r"(p));
    asm("{\n .reg .f16 a, b;\n"
        "  mov.b32 {a, b}, %2;\n"
        "  cvt.f32.f16 %0, a;\n"
        "  cvt.f32.f16 %1, b;\n}" : "=f"(h0), "=f"(h1) : "r"(p));
}

__global__ __launch_bounds__(128, 2)
void ltc_kernel(const float* __restrict__ x,
                const float* __restrict__ gleak,
                const float* __restrict__ vleak,
                const float* __restrict__ cm,
                const float* __restrict__ sigma,
                const float* __restrict__ mu,
                const float* __restrict__ w,
                const float* __restrict__ erev,
                const float* __restrict__ s_sigma,
                const float* __restrict__ s_mu,
                const float* __restrict__ s_w,
                const float* __restrict__ s_erev,
                const float* __restrict__ in_w,
                const float* __restrict__ in_b,
                const float* __restrict__ out_w,
                const float* __restrict__ out_b,
                float* __restrict__ out)
{
    __shared__ __align__(8) float vsm[2][72];  // v[j] at j + 4*(j>>5)

    const int b    = blockIdx.x;
    const int tid  = threadIdx.x;
    const int lane = tid & 31;
    const int wrp  = tid >> 5;
    const int q    = lane >> 4;
    const int u    = (wrp << 4) | (lane & 15);
    const int rbase = 36 * q;

    const float gl   = gleak[u];
    const float cmt  = cm[u] * 6.0f;
    const float glvl = gl * vleak[u];
    const float denc = cmt + gl + 1e-8f;

    // per-(j-pair, u) constants: f32 pairs in 64-bit register pairs
    u64 cs2[16], cc2[16], we2[16], awe2[16];
    float Cd = 0.f, Cn = 0.f;
#pragma unroll
    for (int p = 0; p < 16; p++) {
        int j0 = 32 * q + 2 * p;
        int i0 = j0 * NU + u;
        int i1 = i0 + NU;
        float s0 = 0.5f * sigma[i0], s1 = 0.5f * sigma[i1];
        cs2[p] = pack2(s0, s1);
        cc2[p] = pack2(-mu[i0] * s0, -mu[i1] * s1);
        float w0 = 0.5f * w[i0] * erev[i0];
        float w1 = 0.5f * w[i1] * erev[i1];
        we2[p]  = pack2(w0, w1);
        awe2[p] = pack2(fabsf(w0), fabsf(w1));
        Cd += fabsf(w0) + fabsf(w1);
        Cn += w0 + w1;
    }

    // sensory constants (f32 scalar path, once per timestep)
    float ss[3], sc2[3], swe[3], iw[3], ib[3];
    float sCd = 0.f, sCn = 0.f;
#pragma unroll
    for (int i = 0; i < 3; i++) {
        int ii  = 3 * q + i;
        int idx = ii * NU + u;
        float s = 0.5f * s_sigma[idx];
        ss[i]   = s;
        sc2[i]  = -s_mu[idx] * s;
        float we = 0.5f * s_w[idx] * s_erev[idx];
        swe[i]  = we;
        sCd += fabsf(we);
        sCn += we;
        iw[i] = in_w[ii];
        ib[i] = in_b[ii];
    }

    float ow = 0.f, ob = 0.f;
    if (tid < NM) { ow = out_w[tid]; ob = out_b[tid]; }

    if (q == 0) vsm[0][u + 4 * (u >> 5)] = 0.f;
    float vu = 0.f;

    const float* xb = x + (long long)b * T_LEN * NI + 3 * q;
    float xr0 = xb[0], xr1 = xb[1], xr2 = xb[2];
    float* outp = out + (long long)b * T_LEN * NM;

    // anti-phase stagger: classic placement co-locates bid and bid+148;
    // delay the higher partner ~770 cyc (48 dependent MUFU ops) so the two
    // CTAs' per-unfold serial tails interleave instead of phase-locking.
    if (b >= 148) {
        float d = (float)tid * 1.0e-3f;
#pragma unroll
        for (int i = 0; i < 48; i++)
            asm volatile("tanh.approx.f32 %0, %0;" : "+f"(d));
    }

    __syncthreads();

    const u64 zero2 = pack2(0.f, 0.f);

    for (int t = 0; t < T_LEN; t++) {
        float x0 = xr0, x1 = xr1, x2 = xr2;
        if (t + 1 < T_LEN) {
            const float* xn = xb + (size_t)(t + 1) * NI;
            xr0 = xn[0]; xr1 = xn[1]; xr2 = xn[2];
        }

        // sensory synapses (constant across unfolds)
        float xi0 = fmaf(x0, iw[0], ib[0]);
        float xi1 = fmaf(x1, iw[1], ib[1]);
        float xi2 = fmaf(x2, iw[2], ib[2]);
        float dsa = sCd, nsa = sCn, h;
        h = fast_tanh(fmaf(xi0, ss[0], sc2[0]));
        dsa = fmaf(fabsf(swe[0]), h, dsa);  nsa = fmaf(swe[0], h, nsa);
        h = fast_tanh(fmaf(xi1, ss[1], sc2[1]));
        dsa = fmaf(fabsf(swe[1]), h, dsa);  nsa = fmaf(swe[1], h, nsa);
        h = fast_tanh(fmaf(xi2, ss[2], sc2[2]));
        dsa = fmaf(fabsf(swe[2]), h, dsa);  nsa = fmaf(swe[2], h, nsa);
        dsa += __shfl_xor_sync(0xffffffffu, dsa, 16);
        nsa += __shfl_xor_sync(0xffffffffu, nsa, 16);
        float den_b = denc + dsa;
        float num_b = glvl + nsa;

        // unfolds 0-3: f16x2 tanh (cheap); noise damped by later unfolds
#pragma unroll 1
        for (int k = 0; k < 4; k++) {
            const float* vr = &vsm[k & 1][rbase];
            u64 an2 = zero2, ad2 = zero2;
#pragma unroll
            for (int p = 0; p < 16; p++) {
                float2 vp = *reinterpret_cast<const float2*>(vr + 2 * p);
                u64 arg2 = fma2(pack2(vp.x, vp.y), cs2[p], cc2[p]);
                float h0, h1;
                tanh2_f16(arg2, h0, h1);
                u64 h2 = pack2(h0, h1);
                an2 = fma2(we2[p],  h2, an2);
                ad2 = fma2(awe2[p], h2, ad2);
            }
            float nl, nh, dl, dh;
            unpack2(an2, nl, nh);
            unpack2(ad2, dl, dh);
            float an = Cn + nl + nh;
            float ad = Cd + dl + dh;
            an += __shfl_xor_sync(0xffffffffu, an, 16);
            ad += __shfl_xor_sync(0xffffffffu, ad, 16);
            float num = fmaf(cmt, vu, num_b + an);
            vu = __fdividef(num, den_b + ad);
            if (q == 0) vsm[(k & 1) ^ 1][u + 4 * (u >> 5)] = vu;
            __syncthreads();
        }

        // unfolds 4-5: full f32 tanh (accurate; sets the output precision)
#pragma unroll 1
        for (int k = 4; k < 6; k++) {
            const float* vr = &vsm[k & 1][rbase];
            float an = Cn, ad = Cd;
#pragma unroll
            for (int p = 0; p < 16; p++) {
                float2 vp = *reinterpret_cast<const float2*>(vr + 2 * p);
                float cs0, cs1, cc0, cc1, we0, we1, aw0, aw1;
                unpack2(cs2[p], cs0, cs1);
                unpack2(cc2[p], cc0, cc1);
                unpack2(we2[p], we0, we1);
                unpack2(awe2[p], aw0, aw1);
                float h0 = fast_tanh(fmaf(vp.x, cs0, cc0));
                float h1 = fast_tanh(fmaf(vp.y, cs1, cc1));
                an = fmaf(we0, h0, an);  ad = fmaf(aw0, h0, ad);
                an = fmaf(we1, h1, an);  ad = fmaf(aw1, h1, ad);
            }
            an += __shfl_xor_sync(0xffffffffu, an, 16);
            ad += __shfl_xor_sync(0xffffffffu, ad, 16);
            float num = fmaf(cmt, vu, num_b + an);
            vu = __fdividef(num, den_b + ad);
            if (q == 0) vsm[(k & 1) ^ 1][u + 4 * (u >> 5)] = vu;
            __syncthreads();
        }

        if (tid < NM) outp[(size_t)t * NM + tid] = fmaf(vu, ow, ob);
    }
}

extern "C" void kernel_launch(void* const* d_in, const int* in_sizes, int n_in,
                              void* d_out, int out_size) {
    (void)in_sizes; (void)n_in; (void)out_size;
    ltc_kernel<<<256, 128>>>(
        (const float*)d_in[0],  (const float*)d_in[1],  (const float*)d_in[2],
        (const float*)d_in[3],  (const float*)d_in[4],  (const float*)d_in[5],
        (const float*)d_in[6],  (const float*)d_in[7],  (const float*)d_in[8],
        (const float*)d_in[9],  (const float*)d_in[10], (const float*)d_in[11],
        (const float*)d_in[12], (const float*)d_in[13], (const float*)d_in[14],
        (const float*)d_in[15], (float*)d_out);
}

// round 5
// speedup vs baseline: 1.2448x; 1.2448x over previous
#include <cuda_runtime.h>
#include <cuda_fp16.h>

// LTC RNN, B=256 T=8192 I=6 U=64 M=16, 6 ODE unfolds. MUFU(XU)-bound.
// Round-5: hybrid precision by unfold with a CVT-FREE f16 path (round-4's
// regression traced to cvt ops landing on the XU/conversion port).
//   unfolds 0-3: v, args, tanh, accumulation all fp16 (HFMA2 + tanh.f16x2,
//     zero cvt in the inner loop; split dual accumulators init 0, Cn/Cd
//     added in f32 after one widening per unfold) -> 16 XU ops/warp/unfold.
//   unfolds 4-5: full f32 (tanh.approx.f32) -> sets output precision;
//     fp16 noise from unfolds 0-3 damped ~0.36x (measured round-3->4).
// v ping-pong kept in BOTH f32 (padded) and f16 smem. 1 barrier per unfold.

#define T_LEN 8192
#define NI 6
#define NU 64
#define NM 16

static __device__ __forceinline__ float fast_tanh(float x) {
    float r; asm("tanh.approx.f32 %0, %1;" : "=f"(r) : "f"(x)); return r;
}
static __device__ __forceinline__ __half2 htanh2(__half2 x) {
    unsigned xi = *reinterpret_cast<unsigned*>(&x);
    asm("tanh.approx.f16x2 %0, %0;" : "+r"(xi));
    return *reinterpret_cast<__half2*>(&xi);
}
static __device__ __forceinline__ float fabs_bits(float v) {
    return __int_as_float(__float_as_int(v) & 0x7fffffff);
}

__global__ __launch_bounds__(128, 2)
void ltc_kernel(const float* __restrict__ x,
                const float* __restrict__ gleak,
                const float* __restrict__ vleak,
                const float* __restrict__ cm,
                const float* __restrict__ sigma,
                const float* __restrict__ mu,
                const float* __restrict__ w,
                const float* __restrict__ erev,
                const float* __restrict__ s_sigma,
                const float* __restrict__ s_mu,
                const float* __restrict__ s_w,
                const float* __restrict__ s_erev,
                const float* __restrict__ in_w,
                const float* __restrict__ in_b,
                const float* __restrict__ out_w,
                const float* __restrict__ out_b,
                float* __restrict__ out)
{
    __shared__ __align__(8) float  vsm[2][72];    // f32 v: elem j at j + 4*(j>>5)
    __shared__ __align__(4) __half vsm16[2][NU];  // f16 v mirror

    const int b    = blockIdx.x;
    const int tid  = threadIdx.x;
    const int lane = tid & 31;
    const int wrp  = tid >> 5;
    const int q    = lane >> 4;              // j-half selector
    const int u    = (wrp << 4) | (lane & 15);
    const int rbase = 36 * q;                // padded f32 read base

    const float gl   = gleak[u];
    const float cmt  = cm[u] * 6.0f;
    const float glvl = gl * vleak[u];
    const float denc = cmt + gl + 1e-8f;

    // f32 constants (scalar) for unfolds 4-5; f16 half2 mirrors for 0-3
    float   cs[32], cc[32], we[32];
    __half2 csh[16], cch[16], weh[16];
    float Cd = 0.f, Cn = 0.f;
#pragma unroll
    for (int p = 0; p < 16; p++) {
        int j0 = 32 * q + 2 * p;
        int i0 = j0 * NU + u;
        int i1 = i0 + NU;
        float s0 = 0.5f * sigma[i0], s1 = 0.5f * sigma[i1];
        float c0 = -mu[i0] * s0,     c1 = -mu[i1] * s1;
        float w0 = 0.5f * w[i0] * erev[i0];
        float w1 = 0.5f * w[i1] * erev[i1];
        cs[2*p] = s0; cs[2*p+1] = s1;
        cc[2*p] = c0; cc[2*p+1] = c1;
        we[2*p] = w0; we[2*p+1] = w1;
        csh[p] = __floats2half2_rn(s0, s1);
        cch[p] = __floats2half2_rn(c0, c1);
        weh[p] = __floats2half2_rn(w0, w1);
        Cd += fabsf(w0) + fabsf(w1);
        Cn += w0 + w1;
    }

    // sensory constants (f32 path, once per timestep)
    float ss[3], sc2[3], swe[3], iw[3], ib[3];
    float sCd = 0.f, sCn = 0.f;
#pragma unroll
    for (int i = 0; i < 3; i++) {
        int ii  = 3 * q + i;
        int idx = ii * NU + u;
        float s = 0.5f * s_sigma[idx];
        ss[i]   = s;
        sc2[i]  = -s_mu[idx] * s;
        float wv = 0.5f * s_w[idx] * s_erev[idx];
        swe[i]  = wv;
        sCd += fabsf(wv);
        sCn += wv;
        iw[i] = in_w[ii];
        ib[i] = in_b[ii];
    }

    float ow = 0.f, ob = 0.f;
    if (tid < NM) { ow = out_w[tid]; ob = out_b[tid]; }

    if (q == 0) {
        vsm[0][u + 4 * (u >> 5)] = 0.f;
        vsm16[0][u] = __float2half_rn(0.f);
    }
    float vu = 0.f;

    const float* xb = x + (long long)b * T_LEN * NI + 3 * q;
    float xr0 = xb[0], xr1 = xb[1], xr2 = xb[2];
    float* outp = out + (long long)b * T_LEN * NM;

    __syncthreads();

    const __half2 hz = __floats2half2_rn(0.f, 0.f);

    for (int t = 0; t < T_LEN; t++) {
        float x0 = xr0, x1 = xr1, x2 = xr2;
        if (t + 1 < T_LEN) {
            const float* xn = xb + (size_t)(t + 1) * NI;
            xr0 = xn[0]; xr1 = xn[1]; xr2 = xn[2];
        }

        // sensory synapses (constant across unfolds, f32)
        float xi0 = fmaf(x0, iw[0], ib[0]);
        float xi1 = fmaf(x1, iw[1], ib[1]);
        float xi2 = fmaf(x2, iw[2], ib[2]);
        float dsa = sCd, nsa = sCn, h;
        h = fast_tanh(fmaf(xi0, ss[0], sc2[0]));
        dsa = fmaf(fabsf(swe[0]), h, dsa);  nsa = fmaf(swe[0], h, nsa);
        h = fast_tanh(fmaf(xi1, ss[1], sc2[1]));
        dsa = fmaf(fabsf(swe[1]), h, dsa);  nsa = fmaf(swe[1], h, nsa);
        h = fast_tanh(fmaf(xi2, ss[2], sc2[2]));
        dsa = fmaf(fabsf(swe[2]), h, dsa);  nsa = fmaf(swe[2], h, nsa);
        dsa += __shfl_xor_sync(0xffffffffu, dsa, 16);
        nsa += __shfl_xor_sync(0xffffffffu, nsa, 16);
        float den_b = denc + dsa;
        float num_b = glvl + nsa;

        // unfolds 0-3: pure fp16 synapse math, zero cvt in the loop
#pragma unroll 1
        for (int k = 0; k < 4; k++) {
            const __half2* vr16 =
                reinterpret_cast<const __half2*>(vsm16[k & 1]) + 16 * q;
            __half2 an2a = hz, an2b = hz, ad2a = hz, ad2b = hz;
#pragma unroll
            for (int p = 0; p < 16; p++) {
                __half2 vh = vr16[p];                       // LDS.32 broadcast
                __half2 h2 = htanh2(__hfma2(vh, csh[p], cch[p]));
                __half2 aw = __habs2(weh[p]);
                if (p < 8) {
                    an2a = __hfma2(weh[p], h2, an2a);
                    ad2a = __hfma2(aw,     h2, ad2a);
                } else {
                    an2b = __hfma2(weh[p], h2, an2b);
                    ad2b = __hfma2(aw,     h2, ad2b);
                }
            }
            float2 fn = __half22float2(__hadd2(an2a, an2b));
            float2 fd = __half22float2(__hadd2(ad2a, ad2b));
            float an = Cn + fn.x + fn.y;
            float ad = Cd + fd.x + fd.y;
            an += __shfl_xor_sync(0xffffffffu, an, 16);
            ad += __shfl_xor_sync(0xffffffffu, ad, 16);
            float num = fmaf(cmt, vu, num_b + an);
            vu = __fdividef(num, den_b + ad);
            int nb = (k & 1) ^ 1;
            if (q == 0) {
                vsm[nb][u + 4 * (u >> 5)] = vu;
                vsm16[nb][u] = __float2half_rn(vu);
            }
            __syncthreads();
        }

        // unfolds 4-5: full f32 tanh (sets output precision)
#pragma unroll 1
        for (int k = 4; k < 6; k++) {
            const float* vr = &vsm[k & 1][rbase];
            float an = Cn, ad = Cd;
#pragma unroll
            for (int p = 0; p < 16; p++) {
                float2 vp = *reinterpret_cast<const float2*>(vr + 2 * p);
                float h0 = fast_tanh(fmaf(vp.x, cs[2*p],   cc[2*p]));
                float h1 = fast_tanh(fmaf(vp.y, cs[2*p+1], cc[2*p+1]));
                float w0 = we[2*p], w1 = we[2*p+1];
                an = fmaf(w0, h0, an);  ad = fmaf(fabs_bits(w0), h0, ad);
                an = fmaf(w1, h1, an);  ad = fmaf(fabs_bits(w1), h1, ad);
            }
            an += __shfl_xor_sync(0xffffffffu, an, 16);
            ad += __shfl_xor_sync(0xffffffffu, ad, 16);
            float num = fmaf(cmt, vu, num_b + an);
            vu = __fdividef(num, den_b + ad);
            int nb = (k & 1) ^ 1;
            if (q == 0) {
                vsm[nb][u + 4 * (u >> 5)] = vu;
                vsm16[nb][u] = __float2half_rn(vu);
            }
            __syncthreads();
        }

        if (tid < NM) outp[(size_t)t * NM + tid] = fmaf(vu, ow, ob);
    }
}

extern "C" void kernel_launch(void* const* d_in, const int* in_sizes, int n_in,
                              void* d_out, int out_size) {
    (void)in_sizes; (void)n_in; (void)out_size;
    ltc_kernel<<<256, 128>>>(
        (const float*)d_in[0],  (const float*)d_in[1],  (const float*)d_in[2],
        (const float*)d_in[3],  (const float*)d_in[4],  (const float*)d_in[5],
        (const float*)d_in[6],  (const float*)d_in[7],  (const float*)d_in[8],
        (const float*)d_in[9],  (const float*)d_in[10], (const float*)d_in[11],
        (const float*)d_in[12], (const float*)d_in[13], (const float*)d_in[14],
        (const float*)d_in[15], (float*)d_out);
}